// round 9
// baseline (speedup 1.0000x reference)
#include <cuda_runtime.h>
#include <cuda_fp16.h>
#include <cstdint>

// Problem constants
#define B_    128
#define A_    30
#define T_    65
#define FIN_  4
#define H_    1920
#define G4_   7680
#define NSTEP 64

// GEMM tiling: CTA tile 128(M) x 64(N), K chunk = 64 fp16
#define KCHUNKS  30                 // 1920/64 per phase
#define NSTG     4                  // pipeline stages
#define STAGE_B  40960              // Ah16K + Al16K + W8K
#define SMEMB    (1024 + 1024 + NSTG * STAGE_B)
#define LOFF     14745600u          // per-layer elems in tiled LSTM weights (7680*1920)

// ---------------- device scratch (no allocation allowed) ----------------
__device__ __align__(1024) __half g_wih[2u*7680u*1920u];
__device__ __align__(1024) __half g_whh[2u*7680u*1920u];
__device__ __align__(1024) __half g_w3[1920u*1920u];
__device__ __align__(1024) __half g_xh[245760];    // 30 chunks x 8192 (128 rows x 64 k)
__device__ __align__(1024) __half g_xl[245760];
__device__ __align__(1024) __half g_h0h[245760];
__device__ __align__(1024) __half g_h0l[245760];
__device__ __align__(1024) __half g_h1h[245760];
__device__ __align__(1024) __half g_h1l[245760];
__device__ float g_c[2 * B_ * H_];
__device__ float g_biasI[2 * G4_];                 // gate-interleaved bih+bhh
__device__ float g_r3[3 * B_ * H_];                // W3 split-K slices

// ---------------- PTX helpers ----------------
__device__ __forceinline__ uint32_t smem_u32(const void* p) {
    uint32_t a;
    asm("{ .reg .u64 t; cvta.to.shared.u64 t, %1; cvt.u32.u64 %0, t; }" : "=r"(a) : "l"(p));
    return a;
}
#define MBAR_INIT(addr, cnt) \
    asm volatile("mbarrier.init.shared.b64 [%0], %1;" :: "r"(addr), "r"((uint32_t)(cnt)) : "memory")
#define MBAR_EXPECT_TX(addr, bytes) \
    asm volatile("mbarrier.arrive.expect_tx.shared.b64 _, [%0], %1;" :: "r"(addr), "r"((uint32_t)(bytes)) : "memory")
#define MBAR_ARRIVE(addr) \
    asm volatile("mbarrier.arrive.shared.b64 _, [%0];" :: "r"(addr) : "memory")
#define MBAR_WAIT(addr, par) do { \
    uint32_t _m=(addr), _p=(par), _d; \
    asm volatile("{\n\t.reg .pred p;\n\tmbarrier.try_wait.parity.acquire.cta.shared::cta.b64 p, [%1], %2;\n\tselp.b32 %0,1,0,p;\n\t}" \
        : "=r"(_d) : "r"(_m), "r"(_p) : "memory"); \
    if (!_d) { \
        asm volatile("{\n\t.reg .pred P1;\n\tWL_%=:\n\tmbarrier.try_wait.parity.acquire.cta.shared::cta.b64 P1, [%0], %1, 0x989680;\n\t@P1 bra.uni WD_%=;\n\tbra.uni WL_%=;\n\tWD_%=:\n\t}" \
            :: "r"(_m), "r"(_p) : "memory"); \
    } } while (0)
#define BULK_G2S(dst, src, bytes, mbar) \
    asm volatile("cp.async.bulk.shared::cluster.global.mbarrier::complete_tx::bytes [%0], [%1], %2, [%3];" \
        :: "r"(dst), "l"(src), "r"((uint32_t)(bytes)), "r"(mbar) : "memory")

#define LDSM4(r, addr) \
    asm volatile("ldmatrix.sync.aligned.m8n8.x4.shared.b16 {%0,%1,%2,%3}, [%4];" \
        : "=r"((r)[0]), "=r"((r)[1]), "=r"((r)[2]), "=r"((r)[3]) : "r"(addr))
#define MMA(d, a, b0v, b1v) \
    asm volatile("mma.sync.aligned.m16n8k16.row.col.f32.f16.f16.f32 " \
        "{%0,%1,%2,%3}, {%4,%5,%6,%7}, {%8,%9}, {%0,%1,%2,%3};" \
        : "+f"((d)[0]), "+f"((d)[1]), "+f"((d)[2]), "+f"((d)[3]) \
        : "r"((a)[0]), "r"((a)[1]), "r"((a)[2]), "r"((a)[3]), "r"(b0v), "r"(b1v))

__device__ __forceinline__ uint32_t sw128(uint32_t o) { return o ^ ((o >> 3) & 0x70); }
// activation tile element index (half units): row in [0,128), k in [0,1920)
__device__ __forceinline__ uint32_t act_idx(int row, int k) {
    return (uint32_t)((k >> 6) * 8192) + (sw128((uint32_t)(row * 128 + (k & 63) * 2)) >> 1);
}

// ---------------- weight conversion ----------------
// W3: plain fp32 [1920,1920] -> swizzled fp16 64x64 tiles
__global__ void __launch_bounds__(256) conv_w(
    const float* __restrict__ src, __half* __restrict__ dst, int total)
{
    int i = blockIdx.x * 256 + threadIdx.x;
    if (i >= total) return;
    int n = i / H_, k = i - n * H_;
    uint32_t d = (uint32_t)((n >> 6) * KCHUNKS + (k >> 6)) * 4096
               + (sw128((uint32_t)((n & 63) * 128 + (k & 63) * 2)) >> 1);
    dst[d] = __float2half(src[i]);
}

// LSTM weights [2,7680,1920] -> gate-interleaved rows (n' = unit*4 + gate), swizzled tiles
__global__ void __launch_bounds__(256) conv_lstm(
    const float* __restrict__ src, __half* __restrict__ dst, int total)
{
    int i = blockIdx.x * 256 + threadIdx.x;
    if (i >= total) return;
    int n = i / H_, k = i - n * H_;
    int layer = n / G4_, w = n - layer * G4_;
    int gate = w / H_, unit = w - gate * H_;
    int np = unit * 4 + gate;
    uint32_t d = (uint32_t)layer * LOFF
               + (uint32_t)((np >> 6) * KCHUNKS + (k >> 6)) * 4096
               + (sw128((uint32_t)((np & 63) * 128 + (k & 63) * 2)) >> 1);
    dst[d] = __float2half(src[i]);
}

// interleaved combined bias: biasI[l][unit*4+gate] = bih[l][gate*H+unit] + bhh[...]
__global__ void __launch_bounds__(256) bias_prep(
    const float* __restrict__ bih, const float* __restrict__ bhh, float* __restrict__ biasI)
{
    int i = blockIdx.x * 256 + threadIdx.x;
    if (i >= 2 * G4_) return;
    int layer = i / G4_, w = i - layer * G4_;
    int gate = w / H_, unit = w - gate * H_;
    biasI[layer * G4_ + unit * 4 + gate] = bih[i] + bhh[i];
}

// ---------------- fp16 mma GEMM, optional fused LSTM-cell epilogue ----------------
// A split hi/lo fp16, W single fp16: 2 terms Ah*W + Al*W, fp32 accum.
// cellMode: gate-interleaved N; epilogue computes i,f,g,o -> c,h and writes h hi/lo swizzled.
#define ISSUE_CHUNK(cc, stgA, mbarA) do { \
    int _p = (nph == 2 && (cc) >= KCHUNKS) ? 1 : 0; \
    int _k = (nph == 2) ? ((cc) - _p * KCHUNKS) : (cbeg + (cc)); \
    const __half* _Ah = (_p ? A1h : A0h) + (size_t)_k * 8192; \
    const __half* _Al = (_p ? A1l : A0l) + (size_t)_k * 8192; \
    const __half* _W  = (_p ? W1 : W0) + ((size_t)nt * KCHUNKS + _k) * 4096; \
    MBAR_EXPECT_TX(mbarA, STAGE_B); \
    BULK_G2S((stgA),         _Ah, 16384, mbarA); \
    BULK_G2S((stgA) + 16384, _Al, 16384, mbarA); \
    BULK_G2S((stgA) + 32768, _W,   8192, mbarA); \
} while (0)

__global__ void __launch_bounds__(256, 1) gemm_f16(
    float* __restrict__ C, int ldc, int sliceStride,
    const __half* __restrict__ A0h, const __half* __restrict__ A0l,
    const __half* __restrict__ W0,
    const __half* __restrict__ A1h, const __half* __restrict__ A1l,
    const __half* __restrict__ W1,
    const float* __restrict__ biasI,
    float* __restrict__ cc, __half* __restrict__ hh, __half* __restrict__ hl,
    int nph, int ccnt, int cellMode)
{
    extern __shared__ char smraw[];
    char* sm = (char*)(((unsigned long long)smraw + 1023ull) & ~1023ull);
    const uint32_t sb = smem_u32(sm);
    const uint32_t FULL = sb;
    const uint32_t DONE = sb + 64;
    const uint32_t STG0 = sb + 1024;

    const int tid = threadIdx.x;
    const int wid = tid >> 5, lane = tid & 31;
    const int nt = blockIdx.x;
    const int cbeg = blockIdx.y * ccnt;
    const int NCH = (nph == 2) ? 2 * KCHUNKS : ccnt;
    const int wm = (wid & 3) * 32;
    const int wn = (wid >> 2) * 32;

    if (tid == 0) {
        for (int s = 0; s < NSTG; s++) { MBAR_INIT(FULL + 8 * s, 1); MBAR_INIT(DONE + 8 * s, 8); }
        asm volatile("fence.proxy.async.shared::cta;" ::: "memory");
    }
    __syncthreads();

    if (tid == 0) {
        for (int c = 0; c < NSTG && c < NCH; c++)
            ISSUE_CHUNK(c, STG0 + c * STAGE_B, FULL + 8 * c);
    }

    float acc[2][4][4];
#pragma unroll
    for (int i = 0; i < 2; i++)
#pragma unroll
        for (int jn = 0; jn < 4; jn++)
#pragma unroll
            for (int q = 0; q < 4; q++) acc[i][jn][q] = 0.f;

    const int a_row  = (lane & 7) + ((lane >> 3) & 1) * 8;
    const int a_koff = (lane >> 4) * 16;
    const int w_row  = (lane & 7) + ((lane >> 4) << 3);
    const int w_koff = ((lane >> 3) & 1) * 16;

    for (int c = 0; c < NCH; c++) {
        int s = c & (NSTG - 1);
        MBAR_WAIT(FULL + 8 * s, (c >> 2) & 1);
        uint32_t stg = STG0 + s * STAGE_B;

#pragma unroll
        for (int kb = 0; kb < 4; kb++) {
            uint32_t ah[2][4], al[2][4], wv[2][4];
#pragma unroll
            for (int mt = 0; mt < 2; mt++) {
                uint32_t ad = stg + sw128((uint32_t)((wm + mt * 16 + a_row) * 128 + kb * 32 + a_koff));
                LDSM4(ah[mt], ad);
                LDSM4(al[mt], ad + 16384);
            }
#pragma unroll
            for (int hf = 0; hf < 2; hf++) {
                uint32_t wd = stg + 32768 + sw128((uint32_t)((wn + hf * 16 + w_row) * 128 + kb * 32 + w_koff));
                LDSM4(wv[hf], wd);
            }
#pragma unroll
            for (int mt = 0; mt < 2; mt++) {
#pragma unroll
                for (int hf = 0; hf < 2; hf++) {
                    MMA(acc[mt][2 * hf],     ah[mt], wv[hf][0], wv[hf][1]);
                    MMA(acc[mt][2 * hf + 1], ah[mt], wv[hf][2], wv[hf][3]);
                    MMA(acc[mt][2 * hf],     al[mt], wv[hf][0], wv[hf][1]);
                    MMA(acc[mt][2 * hf + 1], al[mt], wv[hf][2], wv[hf][3]);
                }
            }
        }
        __syncwarp();
        if (lane == 0) MBAR_ARRIVE(DONE + 8 * s);

        int ncn = c + NSTG;
        if (tid == 0 && ncn < NCH) {
            MBAR_WAIT(DONE + 8 * s, (c >> 2) & 1);
            ISSUE_CHUNK(ncn, STG0 + s * STAGE_B, FULL + 8 * s);
        }
    }

    if (cellMode) {
        // gate-interleaved columns: col = 4*unit + gate (i,f,g,o).
        // lane pairs (l, l^1) hold (i,f)/(g,o) for the same unit; exchange via shfl.
#pragma unroll
        for (int mt = 0; mt < 2; mt++) {
            int r0 = wm + mt * 16 + (lane >> 2);
#pragma unroll
            for (int ng = 0; ng < 4; ng++) {
                int colb = nt * 64 + wn + ng * 8 + 2 * (lane & 3);
                float v0 = acc[mt][ng][0] + biasI[colb];
                float v1 = acc[mt][ng][1] + biasI[colb + 1];
                float v2 = acc[mt][ng][2] + biasI[colb];
                float v3 = acc[mt][ng][3] + biasI[colb + 1];
                float p0 = __shfl_xor_sync(0xFFFFFFFFu, v0, 1);
                float p1 = __shfl_xor_sync(0xFFFFFFFFu, v1, 1);
                float p2 = __shfl_xor_sync(0xFFFFFFFFu, v2, 1);
                float p3 = __shfl_xor_sync(0xFFFFFFFFu, v3, 1);
                if (!(lane & 1)) {
                    int u = colb >> 2;
#pragma unroll
                    for (int rr = 0; rr < 2; rr++) {
                        float ig = rr ? v2 : v0, fg = rr ? v3 : v1;
                        float gg = rr ? p2 : p0, og = rr ? p3 : p1;
                        int r = r0 + rr * 8;
                        float si = 1.f / (1.f + expf(-ig));
                        float sf = 1.f / (1.f + expf(-fg));
                        float so = 1.f / (1.f + expf(-og));
                        float tg = tanhf(gg);
                        float cn = sf * cc[r * H_ + u] + si * tg;
                        float hn = so * tanhf(cn);
                        cc[r * H_ + u] = cn;
                        uint32_t ai = act_idx(r, u);
                        __half hv = __float2half(hn);
                        hh[ai] = hv;
                        hl[ai] = __float2half(hn - __half2float(hv));
                    }
                }
            }
        }
        return;
    }

    // plain epilogue (W3 slices): disjoint per blockIdx.y
    float* Cb = C + (size_t)blockIdx.y * sliceStride;
#pragma unroll
    for (int mt = 0; mt < 2; mt++) {
        int r0 = wm + mt * 16 + (lane >> 2);
        float* cp = Cb + (size_t)r0 * ldc;
#pragma unroll
        for (int ng = 0; ng < 4; ng++) {
            int col = nt * 64 + wn + ng * 8 + 2 * (lane & 3);
            *(float2*)(cp + col) = make_float2(acc[mt][ng][0], acc[mt][ng][1]);
            *(float2*)(cp + 8 * ldc + col) = make_float2(acc[mt][ng][2], acc[mt][ng][3]);
        }
    }
}

// ---------------- tail: sum W3 slices + bias + relu, W4 proj + residual + out, then MLP ----------------
__global__ void __launch_bounds__(128) tail_kernel(
    const float* __restrict__ r3, const float* __restrict__ b3,
    const float* __restrict__ W4, const float* __restrict__ b4,
    const float* __restrict__ inputs, float* __restrict__ out,
    __half* __restrict__ xh, __half* __restrict__ xl,
    const float* __restrict__ W1, const float* __restrict__ b1,
    const float* __restrict__ W2, const float* __restrict__ b2,
    int t, int produce, const int* __restrict__ burn, int do_w4)
{
    __shared__ __align__(16) float xs[H_];
    __shared__ float outs[A_ * FIN_];
    __shared__ float W1t[4 * 64];
    __shared__ float W2t[64 * 64];
    __shared__ float b1s[64], b2s[64];
    __shared__ float ins_s[A_ * FIN_];
    __shared__ float x1s[A_ * 64];

    const int b = blockIdx.x, tid = threadIdx.x;
    const int bi = burn ? *burn : 20;

    if (do_w4) {
        for (int k = tid; k < H_; k += 128)
            xs[k] = fmaxf(r3[b * H_ + k] + r3[(B_ + b) * H_ + k] + r3[(2 * B_ + b) * H_ + k] + b3[k], 0.f);
        __syncthreads();
        if (tid < A_ * FIN_) {
            const float4* wp = (const float4*)(W4 + tid * H_);
            const float4* xp = (const float4*)xs;
            float a0 = 0.f, a1 = 0.f, a2 = 0.f, a3 = 0.f;
#pragma unroll 4
            for (int k = 0; k < H_ / 4; k++) {
                float4 w = wp[k]; float4 x = xp[k];
                a0 = fmaf(w.x, x.x, a0); a1 = fmaf(w.y, x.y, a1);
                a2 = fmaf(w.z, x.z, a2); a3 = fmaf(w.w, x.w, a3);
            }
            float acc = b4[tid] + (a0 + a1) + (a2 + a3);
            int a = tid >> 2, f = tid & 3;
            int r = b * A_ + a;
            float insv = (t <= bi) ? inputs[(r * T_ + t) * FIN_ + f]
                                   : out[(r * NSTEP + t - 1) * FIN_ + f];
            float ov = acc + insv;
            out[(r * NSTEP + t) * FIN_ + f] = ov;
            outs[tid] = ov;
        }
        __syncthreads();
    }

    if (produce >= NSTEP) return;

    for (int i = tid; i < 64 * 64; i += 128) {
        int jj = i >> 6, kk = i & 63;
        W2t[kk * 64 + jj] = W2[i];
    }
    for (int i = tid; i < 256; i += 128) {
        int jj = i >> 2, ff = i & 3;
        W1t[ff * 64 + jj] = W1[i];
    }
    if (tid < 64) { b1s[tid] = b1[tid]; b2s[tid] = b2[tid]; }
    if (tid < A_ * FIN_) {
        int a = tid >> 2, f = tid & 3;
        int r = b * A_ + a;
        ins_s[tid] = (produce <= bi) ? inputs[(r * T_ + produce) * FIN_ + f] : outs[tid];
    }
    __syncthreads();

    for (int idx = tid; idx < A_ * 64; idx += 128) {
        int a = idx >> 6, j = idx & 63;
        float v = b1s[j];
#pragma unroll
        for (int f = 0; f < 4; f++) v = fmaf(ins_s[a * 4 + f], W1t[f * 64 + j], v);
        x1s[idx] = fmaxf(v, 0.f);
    }
    __syncthreads();

    for (int idx = tid; idx < A_ * 64; idx += 128) {
        int a = idx >> 6, j = idx & 63;
        float v = b2s[j];
        const float* x1p = x1s + a * 64;
#pragma unroll
        for (int k = 0; k < 64; k++) v = fmaf(x1p[k], W2t[k * 64 + j], v);
        v = fmaxf(v, 0.f);
        uint32_t ai = act_idx(b, a * 64 + j);
        __half hv = __float2half(v);
        xh[ai] = hv;
        xl[ai] = __float2half(v - __half2float(hv));
    }
}

// ---------------- launch ----------------
extern "C" void kernel_launch(void* const* d_in, const int* in_sizes, int n_in,
                              void* d_out, int out_size)
{
    const float* inputs = (const float*)d_in[0];
    const float* W1  = (const float*)d_in[1];
    const float* b1  = (const float*)d_in[2];
    const float* W2  = (const float*)d_in[3];
    const float* b2  = (const float*)d_in[4];
    const float* Wih = (const float*)d_in[5];
    const float* Whh = (const float*)d_in[6];
    const float* bih = (const float*)d_in[7];
    const float* bhh = (const float*)d_in[8];
    const float* W3  = (const float*)d_in[9];
    const float* b3  = (const float*)d_in[10];
    const float* W4  = (const float*)d_in[11];
    const float* b4  = (const float*)d_in[12];
    const int* burn  = (n_in > 14) ? (const int*)d_in[14] : nullptr;
    float* out = (float*)d_out;

    cudaFuncSetAttribute(gemm_f16, cudaFuncAttributeMaxDynamicSharedMemorySize, SMEMB);

    void *pwih, *pwhh, *pw3, *pxh, *pxl, *ph0h, *ph0l, *ph1h, *ph1l, *pc, *pbi, *pr;
    cudaGetSymbolAddress(&pwih, g_wih);
    cudaGetSymbolAddress(&pwhh, g_whh);
    cudaGetSymbolAddress(&pw3, g_w3);
    cudaGetSymbolAddress(&pxh, g_xh);   cudaGetSymbolAddress(&pxl, g_xl);
    cudaGetSymbolAddress(&ph0h, g_h0h); cudaGetSymbolAddress(&ph0l, g_h0l);
    cudaGetSymbolAddress(&ph1h, g_h1h); cudaGetSymbolAddress(&ph1l, g_h1l);
    cudaGetSymbolAddress(&pc, g_c);
    cudaGetSymbolAddress(&pbi, g_biasI);
    cudaGetSymbolAddress(&pr, g_r3);

    __half *wih = (__half*)pwih, *whh = (__half*)pwhh, *w3 = (__half*)pw3;
    __half *xh = (__half*)pxh,   *xl = (__half*)pxl;
    __half *h0h = (__half*)ph0h, *h0l = (__half*)ph0l;
    __half *h1h = (__half*)ph1h, *h1l = (__half*)ph1l;
    float* c0 = (float*)pc;  float* c1 = c0 + B_ * H_;
    float* biasI = (float*)pbi;
    float* r3 = (float*)pr;

    // zero recurrent state
    cudaMemsetAsync(pc, 0, sizeof(float) * 2 * B_ * H_);
    cudaMemsetAsync(ph0h, 0, sizeof(__half) * 245760);
    cudaMemsetAsync(ph0l, 0, sizeof(__half) * 245760);
    cudaMemsetAsync(ph1h, 0, sizeof(__half) * 245760);
    cudaMemsetAsync(ph1l, 0, sizeof(__half) * 245760);

    // convert weights (gate-interleaved for LSTM) + combined interleaved bias
    const int TOT_IH = 2 * G4_ * H_;
    const int TOT_W3 = H_ * H_;
    conv_lstm<<<(TOT_IH + 255) / 256, 256>>>(Wih, wih, TOT_IH);
    conv_lstm<<<(TOT_IH + 255) / 256, 256>>>(Whh, whh, TOT_IH);
    conv_w<<<(TOT_W3 + 255) / 256, 256>>>(W3, w3, TOT_W3);
    bias_prep<<<(2 * G4_ + 255) / 256, 256>>>(bih, bhh, biasI);

    // initial MLP (t=0)
    tail_kernel<<<B_, 128>>>(r3, b3, W4, b4, inputs, out, xh, xl,
                             W1, b1, W2, b2, 0, 0, burn, 0);

    for (int t = 0; t < NSTEP; t++) {
        // layer 0 (fused cell): x@Wih0^T + h0@Whh0^T + bias -> c0, h0
        gemm_f16<<<G4_ / 64, 256, SMEMB>>>(r3, G4_, 0,
            xh, xl, wih, h0h, h0l, whh,
            biasI, c0, h0h, h0l, 2, 0, 1);

        // layer 1 (fused cell): h0@Wih1^T + h1@Whh1^T + bias -> c1, h1
        gemm_f16<<<G4_ / 64, 256, SMEMB>>>(r3, G4_, 0,
            h0h, h0l, wih + LOFF, h1h, h1l, whh + LOFF,
            biasI + G4_, c1, h1h, h1l, 2, 0, 1);

        // W3: split-K=3 into disjoint slices (no atomics, no memset)
        gemm_f16<<<dim3(H_ / 64, 3), 256, SMEMB>>>(r3, H_, B_ * H_,
            h1h, h1l, w3, nullptr, nullptr, nullptr,
            nullptr, nullptr, nullptr, nullptr, 1, 10, 0);

        // tail: slice-sum + bias + relu + W4 + residual + out, then MLP for t+1
        tail_kernel<<<B_, 128>>>(r3, b3, W4, b4, inputs, out, xh, xl,
                                 W1, b1, W2, b2, t, t + 1, burn, 1);
    }
}

// round 10
// speedup vs baseline: 1.3271x; 1.3271x over previous
#include <cuda_runtime.h>
#include <cuda_fp16.h>
#include <cstdint>

// Problem constants
#define B_    128
#define A_    30
#define T_    65
#define FIN_  4
#define H_    1920
#define G4_   7680
#define NSTEP 64

// GEMM tiling: CTA tile 128(M) x 64(N), K chunk = 64 fp16
#define KCHUNKS  30                 // 1920/64 per phase
#define NSTG     4                  // pipeline stages
#define STAGE_B  24576              // A 16K + W 8K
#define SMEMB    (1024 + 1024 + NSTG * STAGE_B)
#define LOFF     14745600u          // per-layer elems in tiled LSTM weights (7680*1920)

// ---------------- device scratch (no allocation allowed) ----------------
__device__ __align__(1024) __half g_wih[2u*7680u*1920u];
__device__ __align__(1024) __half g_whh[2u*7680u*1920u];
__device__ __align__(1024) __half g_w3[1920u*1920u];
__device__ __align__(1024) __half g_x[245760];     // 30 chunks x 8192 (128 rows x 64 k)
__device__ __align__(1024) __half g_h0[245760];
__device__ __align__(1024) __half g_h1[245760];
__device__ float g_c[2 * B_ * H_];
__device__ float g_gates[B_ * G4_];
__device__ float g_r3[3 * B_ * H_];                // W3 split-K disjoint slices

// ---------------- PTX helpers ----------------
__device__ __forceinline__ uint32_t smem_u32(const void* p) {
    uint32_t a;
    asm("{ .reg .u64 t; cvta.to.shared.u64 t, %1; cvt.u32.u64 %0, t; }" : "=r"(a) : "l"(p));
    return a;
}
#define MBAR_INIT(addr, cnt) \
    asm volatile("mbarrier.init.shared.b64 [%0], %1;" :: "r"(addr), "r"((uint32_t)(cnt)) : "memory")
#define MBAR_EXPECT_TX(addr, bytes) \
    asm volatile("mbarrier.arrive.expect_tx.shared.b64 _, [%0], %1;" :: "r"(addr), "r"((uint32_t)(bytes)) : "memory")
#define MBAR_ARRIVE(addr) \
    asm volatile("mbarrier.arrive.shared.b64 _, [%0];" :: "r"(addr) : "memory")
#define MBAR_WAIT(addr, par) do { \
    uint32_t _m=(addr), _p=(par), _d; \
    asm volatile("{\n\t.reg .pred p;\n\tmbarrier.try_wait.parity.acquire.cta.shared::cta.b64 p, [%1], %2;\n\tselp.b32 %0,1,0,p;\n\t}" \
        : "=r"(_d) : "r"(_m), "r"(_p) : "memory"); \
    if (!_d) { \
        asm volatile("{\n\t.reg .pred P1;\n\tWL_%=:\n\tmbarrier.try_wait.parity.acquire.cta.shared::cta.b64 P1, [%0], %1, 0x989680;\n\t@P1 bra.uni WD_%=;\n\tbra.uni WL_%=;\n\tWD_%=:\n\t}" \
            :: "r"(_m), "r"(_p) : "memory"); \
    } } while (0)
#define BULK_G2S(dst, src, bytes, mbar) \
    asm volatile("cp.async.bulk.shared::cluster.global.mbarrier::complete_tx::bytes [%0], [%1], %2, [%3];" \
        :: "r"(dst), "l"(src), "r"((uint32_t)(bytes)), "r"(mbar) : "memory")

#define LDSM4(r, addr) \
    asm volatile("ldmatrix.sync.aligned.m8n8.x4.shared.b16 {%0,%1,%2,%3}, [%4];" \
        : "=r"((r)[0]), "=r"((r)[1]), "=r"((r)[2]), "=r"((r)[3]) : "r"(addr))
#define MMA(d, a, b0v, b1v) \
    asm volatile("mma.sync.aligned.m16n8k16.row.col.f32.f16.f16.f32 " \
        "{%0,%1,%2,%3}, {%4,%5,%6,%7}, {%8,%9}, {%0,%1,%2,%3};" \
        : "+f"((d)[0]), "+f"((d)[1]), "+f"((d)[2]), "+f"((d)[3]) \
        : "r"((a)[0]), "r"((a)[1]), "r"((a)[2]), "r"((a)[3]), "r"(b0v), "r"(b1v))

__device__ __forceinline__ uint32_t sw128(uint32_t o) { return o ^ ((o >> 3) & 0x70); }
// activation tile element index (half units): row in [0,128), k in [0,1920)
__device__ __forceinline__ uint32_t act_idx(int row, int k) {
    return (uint32_t)((k >> 6) * 8192) + (sw128((uint32_t)(row * 128 + (k & 63) * 2)) >> 1);
}

// ---------------- weight conversion: fp32 [N,1920] -> swizzled fp16 64x64 tiles ----------------
__global__ void __launch_bounds__(256) conv_w(
    const float* __restrict__ src, __half* __restrict__ dst, int total)
{
    int i = blockIdx.x * 256 + threadIdx.x;
    if (i >= total) return;
    int n = i / H_, k = i - n * H_;
    uint32_t d = (uint32_t)((n >> 6) * KCHUNKS + (k >> 6)) * 4096
               + (sw128((uint32_t)((n & 63) * 128 + (k & 63) * 2)) >> 1);
    dst[d] = __float2half(src[i]);
}

// ---------------- fp16 mma GEMM: C[128, nt*64..] = sum_ph A_ph @ W_ph^T (+bias) ----------------
// Single fp16 A and W, fp32 accumulate. 1 term per operand pair.
#define ISSUE_CHUNK(cc, stgA, mbarA) do { \
    int _p = (nph == 2 && (cc) >= KCHUNKS) ? 1 : 0; \
    int _k = (nph == 2) ? ((cc) - _p * KCHUNKS) : (cbeg + (cc)); \
    const __half* _A = (_p ? A1 : A0) + (size_t)_k * 8192; \
    const __half* _W = (_p ? W1 : W0) + ((size_t)nt * KCHUNKS + _k) * 4096; \
    MBAR_EXPECT_TX(mbarA, STAGE_B); \
    BULK_G2S((stgA),         _A, 16384, mbarA); \
    BULK_G2S((stgA) + 16384, _W,  8192, mbarA); \
} while (0)

__global__ void __launch_bounds__(256, 1) gemm_f16(
    float* __restrict__ C, int ldc, int sliceStride,
    const __half* __restrict__ A0, const __half* __restrict__ W0,
    const __half* __restrict__ A1, const __half* __restrict__ W1,
    const float* __restrict__ bias0, const float* __restrict__ bias1,
    int nph, int ccnt)
{
    extern __shared__ char smraw[];
    char* sm = (char*)(((unsigned long long)smraw + 1023ull) & ~1023ull);
    const uint32_t sb = smem_u32(sm);
    const uint32_t FULL = sb;
    const uint32_t DONE = sb + 64;
    const uint32_t STG0 = sb + 1024;

    const int tid = threadIdx.x;
    const int wid = tid >> 5, lane = tid & 31;
    const int nt = blockIdx.x;
    const int cbeg = blockIdx.y * ccnt;
    const int NCH = (nph == 2) ? 2 * KCHUNKS : ccnt;
    const int wm = (wid & 3) * 32;
    const int wn = (wid >> 2) * 32;

    if (tid == 0) {
        for (int s = 0; s < NSTG; s++) { MBAR_INIT(FULL + 8 * s, 1); MBAR_INIT(DONE + 8 * s, 8); }
        asm volatile("fence.proxy.async.shared::cta;" ::: "memory");
    }
    __syncthreads();

    if (tid == 0) {
        for (int c = 0; c < NSTG && c < NCH; c++)
            ISSUE_CHUNK(c, STG0 + c * STAGE_B, FULL + 8 * c);
    }

    float acc[2][4][4];
#pragma unroll
    for (int i = 0; i < 2; i++)
#pragma unroll
        for (int jn = 0; jn < 4; jn++)
#pragma unroll
            for (int q = 0; q < 4; q++) acc[i][jn][q] = 0.f;

    const int a_row  = (lane & 7) + ((lane >> 3) & 1) * 8;
    const int a_koff = (lane >> 4) * 16;
    const int w_row  = (lane & 7) + ((lane >> 4) << 3);
    const int w_koff = ((lane >> 3) & 1) * 16;

    for (int c = 0; c < NCH; c++) {
        int s = c & (NSTG - 1);
        MBAR_WAIT(FULL + 8 * s, (c >> 2) & 1);
        uint32_t stg = STG0 + s * STAGE_B;

#pragma unroll
        for (int kb = 0; kb < 4; kb++) {
            uint32_t av[2][4], wv[2][4];
#pragma unroll
            for (int mt = 0; mt < 2; mt++) {
                uint32_t ad = stg + sw128((uint32_t)((wm + mt * 16 + a_row) * 128 + kb * 32 + a_koff));
                LDSM4(av[mt], ad);
            }
#pragma unroll
            for (int hf = 0; hf < 2; hf++) {
                uint32_t wd = stg + 16384 + sw128((uint32_t)((wn + hf * 16 + w_row) * 128 + kb * 32 + w_koff));
                LDSM4(wv[hf], wd);
            }
#pragma unroll
            for (int mt = 0; mt < 2; mt++) {
#pragma unroll
                for (int hf = 0; hf < 2; hf++) {
                    MMA(acc[mt][2 * hf],     av[mt], wv[hf][0], wv[hf][1]);
                    MMA(acc[mt][2 * hf + 1], av[mt], wv[hf][2], wv[hf][3]);
                }
            }
        }
        __syncwarp();
        if (lane == 0) MBAR_ARRIVE(DONE + 8 * s);

        int ncn = c + NSTG;
        if (tid == 0 && ncn < NCH) {
            MBAR_WAIT(DONE + 8 * s, (c >> 2) & 1);
            ISSUE_CHUNK(ncn, STG0 + s * STAGE_B, FULL + 8 * s);
        }
    }

    // epilogue: lane l holds rows (l>>2, +8), cols 2(l&3), +1 per n8 group.
    // sliceStride>0: disjoint per-blockIdx.y slice (W3); else bias add (LSTM gates).
    float* Cb = C + (size_t)blockIdx.y * sliceStride;
#pragma unroll
    for (int mt = 0; mt < 2; mt++) {
        int r0 = wm + mt * 16 + (lane >> 2);
        float* cp = Cb + (size_t)r0 * ldc;
#pragma unroll
        for (int ng = 0; ng < 4; ng++) {
            int col = nt * 64 + wn + ng * 8 + 2 * (lane & 3);
            float b0v = 0.f, b1v = 0.f;
            if (bias0) { b0v = bias0[col] + bias1[col]; b1v = bias0[col + 1] + bias1[col + 1]; }
            *(float2*)(cp + col) = make_float2(acc[mt][ng][0] + b0v, acc[mt][ng][1] + b1v);
            *(float2*)(cp + 8 * ldc + col) = make_float2(acc[mt][ng][2] + b0v, acc[mt][ng][3] + b1v);
        }
    }
}

// ---------------- LSTM cell: gates -> new c (fp32) + new h (swizzled fp16) ----------------
__global__ void __launch_bounds__(256) lstm_cell(
    const float* __restrict__ gates, float* __restrict__ c, __half* __restrict__ h)
{
    int idx = blockIdx.x * 256 + threadIdx.x;   // < 128*1920
    int b = idx / H_;
    int jj = idx - b * H_;
    const float* g = gates + b * G4_;
    float ig = g[jj], fg = g[H_ + jj], gg = g[2 * H_ + jj], og = g[3 * H_ + jj];
    float si = 1.f / (1.f + expf(-ig));
    float sf = 1.f / (1.f + expf(-fg));
    float so = 1.f / (1.f + expf(-og));
    float tg = tanhf(gg);
    float cn = sf * c[idx] + si * tg;
    float hn = so * tanhf(cn);
    c[idx] = cn;
    h[act_idx(b, jj)] = __float2half(hn);
}

// ---------------- tail: sum W3 slices + bias + relu, W4 + residual + out, then MLP ----------------
__global__ void __launch_bounds__(128) tail_kernel(
    const float* __restrict__ r3, const float* __restrict__ b3,
    const float* __restrict__ W4, const float* __restrict__ b4,
    const float* __restrict__ inputs, float* __restrict__ out,
    __half* __restrict__ x,
    const float* __restrict__ W1, const float* __restrict__ b1,
    const float* __restrict__ W2, const float* __restrict__ b2,
    int t, int produce, const int* __restrict__ burn, int do_w4)
{
    __shared__ __align__(16) float xs[H_];
    __shared__ float outs[A_ * FIN_];
    __shared__ float W1t[4 * 64];
    __shared__ float W2t[64 * 64];
    __shared__ float b1s[64], b2s[64];
    __shared__ float ins_s[A_ * FIN_];
    __shared__ float x1s[A_ * 64];

    const int b = blockIdx.x, tid = threadIdx.x;
    const int bi = burn ? *burn : 20;

    if (do_w4) {
        for (int k = tid; k < H_; k += 128)
            xs[k] = fmaxf(r3[b * H_ + k] + r3[(B_ + b) * H_ + k] + r3[(2 * B_ + b) * H_ + k] + b3[k], 0.f);
        __syncthreads();
        if (tid < A_ * FIN_) {
            const float4* wp = (const float4*)(W4 + tid * H_);
            const float4* xp = (const float4*)xs;
            float a0 = 0.f, a1 = 0.f, a2 = 0.f, a3 = 0.f;
#pragma unroll 4
            for (int k = 0; k < H_ / 4; k++) {
                float4 w = wp[k]; float4 xv = xp[k];
                a0 = fmaf(w.x, xv.x, a0); a1 = fmaf(w.y, xv.y, a1);
                a2 = fmaf(w.z, xv.z, a2); a3 = fmaf(w.w, xv.w, a3);
            }
            float acc = b4[tid] + (a0 + a1) + (a2 + a3);
            int a = tid >> 2, f = tid & 3;
            int r = b * A_ + a;
            float insv = (t <= bi) ? inputs[(r * T_ + t) * FIN_ + f]
                                   : out[(r * NSTEP + t - 1) * FIN_ + f];
            float ov = acc + insv;
            out[(r * NSTEP + t) * FIN_ + f] = ov;
            outs[tid] = ov;
        }
        __syncthreads();
    }

    if (produce >= NSTEP) return;

    for (int i = tid; i < 64 * 64; i += 128) {
        int jj = i >> 6, kk = i & 63;
        W2t[kk * 64 + jj] = W2[i];
    }
    for (int i = tid; i < 256; i += 128) {
        int jj = i >> 2, ff = i & 3;
        W1t[ff * 64 + jj] = W1[i];
    }
    if (tid < 64) { b1s[tid] = b1[tid]; b2s[tid] = b2[tid]; }
    if (tid < A_ * FIN_) {
        int a = tid >> 2, f = tid & 3;
        int r = b * A_ + a;
        ins_s[tid] = (produce <= bi) ? inputs[(r * T_ + produce) * FIN_ + f] : outs[tid];
    }
    __syncthreads();

    for (int idx = tid; idx < A_ * 64; idx += 128) {
        int a = idx >> 6, j = idx & 63;
        float v = b1s[j];
#pragma unroll
        for (int f = 0; f < 4; f++) v = fmaf(ins_s[a * 4 + f], W1t[f * 64 + j], v);
        x1s[idx] = fmaxf(v, 0.f);
    }
    __syncthreads();

    for (int idx = tid; idx < A_ * 64; idx += 128) {
        int a = idx >> 6, j = idx & 63;
        float v = b2s[j];
        const float* x1p = x1s + a * 64;
#pragma unroll
        for (int k = 0; k < 64; k++) v = fmaf(x1p[k], W2t[k * 64 + j], v);
        v = fmaxf(v, 0.f);
        x[act_idx(b, a * 64 + j)] = __float2half(v);
    }
}

// ---------------- launch ----------------
extern "C" void kernel_launch(void* const* d_in, const int* in_sizes, int n_in,
                              void* d_out, int out_size)
{
    const float* inputs = (const float*)d_in[0];
    const float* W1  = (const float*)d_in[1];
    const float* b1  = (const float*)d_in[2];
    const float* W2  = (const float*)d_in[3];
    const float* b2  = (const float*)d_in[4];
    const float* Wih = (const float*)d_in[5];
    const float* Whh = (const float*)d_in[6];
    const float* bih = (const float*)d_in[7];
    const float* bhh = (const float*)d_in[8];
    const float* W3  = (const float*)d_in[9];
    const float* b3  = (const float*)d_in[10];
    const float* W4  = (const float*)d_in[11];
    const float* b4  = (const float*)d_in[12];
    const int* burn  = (n_in > 14) ? (const int*)d_in[14] : nullptr;
    float* out = (float*)d_out;

    cudaFuncSetAttribute(gemm_f16, cudaFuncAttributeMaxDynamicSharedMemorySize, SMEMB);

    void *pwih, *pwhh, *pw3, *px, *ph0, *ph1, *pc, *pg, *pr;
    cudaGetSymbolAddress(&pwih, g_wih);
    cudaGetSymbolAddress(&pwhh, g_whh);
    cudaGetSymbolAddress(&pw3, g_w3);
    cudaGetSymbolAddress(&px, g_x);
    cudaGetSymbolAddress(&ph0, g_h0);
    cudaGetSymbolAddress(&ph1, g_h1);
    cudaGetSymbolAddress(&pc, g_c);
    cudaGetSymbolAddress(&pg, g_gates);
    cudaGetSymbolAddress(&pr, g_r3);

    __half *wih = (__half*)pwih, *whh = (__half*)pwhh, *w3 = (__half*)pw3;
    __half *x = (__half*)px, *h0 = (__half*)ph0, *h1 = (__half*)ph1;
    float* c0 = (float*)pc;  float* c1 = c0 + B_ * H_;
    float* gates = (float*)pg;
    float* r3 = (float*)pr;

    // zero recurrent state
    cudaMemsetAsync(pc, 0, sizeof(float) * 2 * B_ * H_);
    cudaMemsetAsync(ph0, 0, sizeof(__half) * 245760);
    cudaMemsetAsync(ph1, 0, sizeof(__half) * 245760);

    // convert weights to pre-swizzled fp16 tiles (once per launch)
    const int TOT_IH = 2 * G4_ * H_;
    const int TOT_W3 = H_ * H_;
    conv_w<<<(TOT_IH + 255) / 256, 256>>>(Wih, wih, TOT_IH);
    conv_w<<<(TOT_IH + 255) / 256, 256>>>(Whh, whh, TOT_IH);
    conv_w<<<(TOT_W3 + 255) / 256, 256>>>(W3, w3, TOT_W3);

    // initial MLP (t=0)
    tail_kernel<<<B_, 128>>>(r3, b3, W4, b4, inputs, out, x,
                             W1, b1, W2, b2, 0, 0, burn, 0);

    for (int t = 0; t < NSTEP; t++) {
        // layer 0: gates = x@Wih0^T + h0@Whh0^T + biases
        gemm_f16<<<G4_ / 64, 256, SMEMB>>>(gates, G4_, 0,
            x, wih, h0, whh, bih, bhh, 2, 0);
        lstm_cell<<<960, 256>>>(gates, c0, h0);

        // layer 1: gates = h0@Wih1^T + h1@Whh1^T + biases
        gemm_f16<<<G4_ / 64, 256, SMEMB>>>(gates, G4_, 0,
            h0, wih + LOFF, h1, whh + LOFF, bih + G4_, bhh + G4_, 2, 0);
        lstm_cell<<<960, 256>>>(gates, c1, h1);

        // W3: split-K=3, disjoint slices (summed in tail; no memset/atomics)
        gemm_f16<<<dim3(H_ / 64, 3), 256, SMEMB>>>(r3, H_, B_ * H_,
            h1, w3, nullptr, nullptr, nullptr, nullptr, 1, 10);

        // tail: slice-sum + bias + relu + W4 + residual + out, then MLP for t+1
        tail_kernel<<<B_, 128>>>(r3, b3, W4, b4, inputs, out, x,
                                 W1, b1, W2, b2, t, t + 1, burn, 1);
    }
}